// round 1
// baseline (speedup 1.0000x reference)
#include <cuda_runtime.h>
#include <cuda_pipeline.h>
#include <math.h>

#define B_ 16
#define A_ 256
#define N_ 64
#define G_ 64
#define F_ 128
#define ROWS_TOTAL (B_*A_)   // 4096

// scratch for y = x @ w_in2f  (2 MB, static device array: allocation-free)
__device__ float g_y[ROWS_TOTAL * F_];

__device__ __forceinline__ float sspf(float x) {
    // softplus(x) - ln 2, numerically stable
    float ax = fabsf(x);
    return fmaxf(x, 0.0f) + __logf(1.0f + __expf(-ax)) - 0.6931471805599453f;
}

// ---------------------------------------------------------------------------
// Kernel 1: y[row][f] = sum_k x[row][k] * w_in2f[k][f]   (4096 x 128 @ 128x128)
// ---------------------------------------------------------------------------
__global__ void in2f_kernel(const float* __restrict__ x,
                            const float* __restrict__ w) {
    __shared__ float sx[F_];
    int row = blockIdx.x;
    int t = threadIdx.x;  // 128 threads
    sx[t] = x[row * F_ + t];
    __syncthreads();
    float acc = 0.f;
#pragma unroll 8
    for (int k = 0; k < F_; k++) {
        acc += sx[k] * w[k * F_ + t];
    }
    g_y[row * F_ + t] = acc;
}

// ---------------------------------------------------------------------------
// Kernel 2: fused CFConv per atom.
//   GEMM1: H = ssp(f_ij @ fw1 + fb1)        [64 x 128], k=64
//   GEMM2: W = H @ fw2 + fb2                [64 x 128], k=128
//   agg[f] = sum_n W[n][f] * cc[n] * y[neighbor[n]][f]
//   out    = ssp(agg @ w_f2out + b_f2out)
// ---------------------------------------------------------------------------

// shared layout (floats)
#define SA_OFF    0                      // [64][68]  f_ij transposed (sA[g*68+n])
#define SW1_OFF   (SA_OFF + 64*68)       // [64][128] fw1
#define SHT_OFF   (SW1_OFF + 64*128)     // [128][68] H transposed (sHT[f*68+n])
#define SW2_OFF   (SHT_OFF + 128*68)     // [128][128] fw2
#define SY_OFF    (SW2_OFF + 128*128)    // [64][128] gathered y rows
#define SRED_OFF  (SY_OFF + 64*128)      // [16][128] reduction buffer
#define SCC_OFF   (SRED_OFF + 16*128)    // [64] cutoff*mask
#define SB1_OFF   (SCC_OFF + 64)         // [128]
#define SB2_OFF   (SB1_OFF + 128)        // [128]
#define SACC_OFF  (SB2_OFF + 128)        // [128]
#define SMEM_FLOATS (SACC_OFF + 128)
#define SMEM_BYTES  (SMEM_FLOATS * 4)

__global__ __launch_bounds__(256, 1)
void cfconv_kernel(const float* __restrict__ r_ij,
                   const float* __restrict__ f_ij,
                   const int*   __restrict__ neighbors,
                   const float* __restrict__ pmask,
                   const float* __restrict__ fw1,
                   const float* __restrict__ fb1,
                   const float* __restrict__ fw2,
                   const float* __restrict__ fb2,
                   const float* __restrict__ w_f2out,
                   const float* __restrict__ b_f2out,
                   float* __restrict__ out) {
    extern __shared__ float sm[];
    float* sA   = sm + SA_OFF;
    float* sW1  = sm + SW1_OFF;
    float* sHT  = sm + SHT_OFF;
    float* sW2  = sm + SW2_OFF;
    float* sY   = sm + SY_OFF;
    float* sRed = sm + SRED_OFF;
    float* sCC  = sm + SCC_OFF;
    float* sB1  = sm + SB1_OFF;
    float* sB2  = sm + SB2_OFF;
    float* sAcc = sm + SACC_OFF;

    const int cta = blockIdx.x;     // b*A + a
    const int tid = threadIdx.x;
    const int b   = cta >> 8;       // A_ = 256

    // ---- async loads (overlap with GEMM1): fw2 + gathered y rows ----
    {
        // fw2: 16384 floats = 4096 float4; 16 per thread, coalesced
#pragma unroll
        for (int q = 0; q < 16; q++) {
            int f4 = q * 256 + tid;
            __pipeline_memcpy_async(sW2 + f4 * 4, fw2 + f4 * 4, 16);
        }
        // y gather: 4 threads per neighbor row, 32 floats each
        int n  = tid >> 2;
        int ch = tid & 3;
        int nb = neighbors[cta * N_ + n];
        const float* src = g_y + (size_t)(b * A_ + nb) * F_ + ch * 32;
        float* dst = sY + n * F_ + ch * 32;
#pragma unroll
        for (int q = 0; q < 8; q++) {
            __pipeline_memcpy_async(dst + q * 4, src + q * 4, 16);
        }
        __pipeline_commit();
    }

    // ---- sync loads: f_ij (transposed), fw1, biases, cutoff ----
    {
        const float* fsrc = f_ij + (size_t)cta * (N_ * G_);
#pragma unroll
        for (int it = 0; it < 16; it++) {
            int idx = tid + it * 256;       // 0..4095
            int n = idx >> 6, g = idx & 63;
            sA[g * 68 + n] = fsrc[idx];     // transpose store (pad 68)
        }
#pragma unroll
        for (int q = 0; q < 8; q++) {       // fw1: 2048 float4
            int f4 = q * 256 + tid;
            *(float4*)(sW1 + f4 * 4) = *(const float4*)(fw1 + f4 * 4);
        }
        if (tid < 128) {
            sB1[tid] = fb1[tid];
            sB2[tid] = fb2[tid];
        }
        if (tid < 64) {
            float r = r_ij[cta * N_ + tid];
            float m = pmask[cta * N_ + tid];
            float c = (r < 5.0f) ? 0.5f * (cosf(r * 0.6283185307179586f) + 1.0f) : 0.0f;
            sCC[tid] = c * m;
        }
    }
    __syncthreads();

    const int tr = tid >> 4;        // 0..15
    const int tc = tid & 15;        // 0..15
    const int r0 = tr * 4;          // 4 rows
    const int c0 = tc * 4;          // cols c0..c0+3 and c0+64..c0+67

    float acc[4][8];
#pragma unroll
    for (int i = 0; i < 4; i++)
#pragma unroll
        for (int j = 0; j < 8; j++) acc[i][j] = 0.f;

    // ---- GEMM1: H = f_ij @ fw1 (k = 64) ----
#pragma unroll 4
    for (int k = 0; k < G_; k++) {
        float4 av = *(const float4*)(sA + k * 68 + r0);
        float4 b0 = *(const float4*)(sW1 + k * F_ + c0);
        float4 b1 = *(const float4*)(sW1 + k * F_ + c0 + 64);
        float a[4] = {av.x, av.y, av.z, av.w};
        float bb[8] = {b0.x, b0.y, b0.z, b0.w, b1.x, b1.y, b1.z, b1.w};
#pragma unroll
        for (int i = 0; i < 4; i++)
#pragma unroll
            for (int j = 0; j < 8; j++) acc[i][j] += a[i] * bb[j];
    }

    // ssp(H + fb1), store transposed into sHT
#pragma unroll
    for (int j = 0; j < 8; j++) {
        int c = (j < 4) ? (c0 + j) : (c0 + 60 + j);
        float bias = sB1[c];
#pragma unroll
        for (int i = 0; i < 4; i++) {
            sHT[c * 68 + r0 + i] = sspf(acc[i][j] + bias);
        }
    }
    __pipeline_wait_prior(0);       // fw2 + sY landed
    __syncthreads();

    // ---- GEMM2: W = H @ fw2 (k = 128) ----
#pragma unroll
    for (int i = 0; i < 4; i++)
#pragma unroll
        for (int j = 0; j < 8; j++) acc[i][j] = 0.f;

#pragma unroll 4
    for (int k = 0; k < F_; k++) {
        float4 av = *(const float4*)(sHT + k * 68 + r0);
        float4 b0 = *(const float4*)(sW2 + k * F_ + c0);
        float4 b1 = *(const float4*)(sW2 + k * F_ + c0 + 64);
        float a[4] = {av.x, av.y, av.z, av.w};
        float bb[8] = {b0.x, b0.y, b0.z, b0.w, b1.x, b1.y, b1.z, b1.w};
#pragma unroll
        for (int i = 0; i < 4; i++)
#pragma unroll
            for (int j = 0; j < 8; j++) acc[i][j] += a[i] * bb[j];
    }

    // ---- epilogue: (W + fb2) * cc[n] * y_nbh, partial-sum over this thread's rows ----
    float p[8];
#pragma unroll
    for (int j = 0; j < 8; j++) p[j] = 0.f;

    float bias[8];
#pragma unroll
    for (int j = 0; j < 8; j++) {
        int c = (j < 4) ? (c0 + j) : (c0 + 60 + j);
        bias[j] = sB2[c];
    }
#pragma unroll
    for (int i = 0; i < 4; i++) {
        int r = r0 + i;
        float ccv = sCC[r];
        float4 y0 = *(const float4*)(sY + r * F_ + c0);
        float4 y1 = *(const float4*)(sY + r * F_ + c0 + 64);
        float yv[8] = {y0.x, y0.y, y0.z, y0.w, y1.x, y1.y, y1.z, y1.w};
#pragma unroll
        for (int j = 0; j < 8; j++) {
            p[j] += (acc[i][j] + bias[j]) * ccv * yv[j];
        }
    }
    // write partials, reduce across 16 thread-rows
#pragma unroll
    for (int j = 0; j < 8; j++) {
        int c = (j < 4) ? (c0 + j) : (c0 + 60 + j);
        sRed[tr * F_ + c] = p[j];
    }
    __syncthreads();
    if (tid < F_) {
        float s = 0.f;
#pragma unroll
        for (int q = 0; q < 16; q++) s += sRed[q * F_ + tid];
        sAcc[tid] = s;
    }
    __syncthreads();

    // ---- f2out: out = ssp(agg @ w_f2out + b_f2out) ----
    if (tid < F_) {
        float v = b_f2out[tid];
#pragma unroll 8
        for (int k = 0; k < F_; k++) {
            v += sAcc[k] * w_f2out[k * F_ + tid];
        }
        out[(size_t)cta * F_ + tid] = sspf(v);
    }
}

// ---------------------------------------------------------------------------
extern "C" void kernel_launch(void* const* d_in, const int* in_sizes, int n_in,
                              void* d_out, int out_size) {
    const float* x        = (const float*)d_in[0];
    const float* r_ij     = (const float*)d_in[1];
    const float* f_ij     = (const float*)d_in[2];
    const int*   neighbors= (const int*)  d_in[3];
    const float* pmask    = (const float*)d_in[4];
    const float* fw1      = (const float*)d_in[5];
    const float* fb1      = (const float*)d_in[6];
    const float* fw2      = (const float*)d_in[7];
    const float* fb2      = (const float*)d_in[8];
    const float* w_in2f   = (const float*)d_in[9];
    const float* w_f2out  = (const float*)d_in[10];
    const float* b_f2out  = (const float*)d_in[11];
    float* out = (float*)d_out;

    // opt into large dynamic smem (idempotent; not a stream op, capture-safe)
    cudaFuncSetAttribute(cfconv_kernel,
                         cudaFuncAttributeMaxDynamicSharedMemorySize, SMEM_BYTES);

    in2f_kernel<<<ROWS_TOTAL, F_>>>(x, w_in2f);
    cfconv_kernel<<<ROWS_TOTAL, 256, SMEM_BYTES>>>(
        r_ij, f_ij, neighbors, pmask, fw1, fb1, fw2, fb2,
        w_f2out, b_f2out, out);
}